// round 13
// baseline (speedup 1.0000x reference)
#include <cuda_runtime.h>
#include <cuda_fp16.h>
#include <cstdint>

#define NB   2
#define NN   8192
#define NK   16
#define HD   128
#define CIN  64
#define COUT 128
#define NPTS (NB * NN)   // 16384
#define NCAT 384         // QA|KA|V concatenated

// ---------------- helpers ----------------------------------------------------
__device__ __forceinline__ uint32_t smem_to_u32(const void* p) {
    uint32_t a;
    asm("{ .reg .u64 t; cvta.to.shared.u64 t, %1; cvt.u32.u64 %0, t; }"
        : "=r"(a) : "l"(p));
    return a;
}
#define LDSM_X4(r0, r1, r2, r3, addr) \
    asm volatile("ldmatrix.sync.aligned.m8n8.x4.shared.b16 {%0,%1,%2,%3}, [%4];" \
                 : "=r"(r0), "=r"(r1), "=r"(r2), "=r"(r3) : "r"(addr))
#define MMA_F16(c, a, b0, b1) \
    asm volatile("mma.sync.aligned.m16n8k16.row.col.f32.f16.f16.f32 " \
                 "{%0,%1,%2,%3}, {%4,%5,%6,%7}, {%8,%9}, {%0,%1,%2,%3};" \
                 : "+f"((c)[0]), "+f"((c)[1]), "+f"((c)[2]), "+f"((c)[3]) \
                 : "r"((a)[0]), "r"((a)[1]), "r"((a)[2]), "r"((a)[3]), \
                   "r"(b0), "r"(b1))
#define CP_ASYNC16(dst, src) \
    asm volatile("cp.async.cg.shared.global [%0], [%1], 16;" \
                 :: "r"(dst), "l"(src) : "memory")
#define CP_COMMIT() asm volatile("cp.async.commit_group;" ::: "memory")
#define CP_WAIT(n)  asm volatile("cp.async.wait_group %0;" :: "n"(n) : "memory")
#define SWZ(b) ((b) ^ (((b) >> 3) & 0x70))

__device__ __forceinline__ float4 ldh4(const __half* p) {
    uint2 u = *(const uint2*)p;
    float2 fa = __half22float2(*(__half2*)&u.x);
    float2 fb = __half22float2(*(__half2*)&u.y);
    return make_float4(fa.x, fa.y, fb.x, fb.y);
}
__device__ __forceinline__ __half2 shfl_h2(__half2 v, int src) {
    uint32_t u = *(uint32_t*)&v;
    u = __shfl_sync(0xffffffffu, u, src);
    return *(__half2*)&u;
}
__device__ __forceinline__ __half2 shfl_xor_h2(__half2 v, int m) {
    uint32_t u = *(uint32_t*)&v;
    u = __shfl_xor_sync(0xffffffffu, u, m);
    return *(__half2*)&u;
}

// ---------------- scratch globals --------------------------------------------
__device__ float g_P2A1[3 * HD];
__device__ float g_c1[HD];
__device__ __align__(16) __half g_QKVh[NPTS * NCAT];       // fp16 [QA|KA|V]
__device__ __align__(16) __half g_feath[NPTS * CIN];       // fp16 features
__device__ __align__(16) __half g_WcatPh[NCAT * CIN];      // fp16 [n][k] folded
__device__ __align__(16) __half g_WoutPh[HD * HD];         // fp16 [n][k]
__device__ __align__(16) __half g_fusedh[NPTS * HD];       // fp16 fused

// ---------------- setup + feature convert (merged, one launch) ---------------
#define SETUP_BLKS (CIN + 1 + HD)          // 193
#define CONV_ITEMS (NPTS * CIN / 4)        // 262144
__global__ void setup_kernel(const float* __restrict__ Wq, const float* __restrict__ Wk,
                             const float* __restrict__ Wv, const float* __restrict__ A1,
                             const float* __restrict__ P2, const float* __restrict__ b1,
                             const float* __restrict__ bp2, const float* __restrict__ Wout,
                             const float* __restrict__ feat) {
    int c = threadIdx.x;          // 0..383
    int blk = blockIdx.x;
    if (blk < CIN) {
        int r = blk;
        float acc;
        if (c < HD) {
            acc = 0.f;
            for (int j = 0; j < HD; j++) acc = fmaf(Wq[r * HD + j], A1[j * HD + c], acc);
        } else if (c < 2 * HD) {
            int cc = c - HD;
            acc = 0.f;
            for (int j = 0; j < HD; j++) acc = fmaf(Wk[r * HD + j], A1[j * HD + cc], acc);
        } else {
            acc = Wv[r * HD + (c - 2 * HD)];
        }
        g_WcatPh[c * CIN + r] = __float2half_rn(acc);
    } else if (blk == CIN) {
        if (c < HD) {
            for (int rr = 0; rr < 3; rr++) {
                float acc = 0.f;
                for (int j = 0; j < HD; j++) acc = fmaf(P2[rr * HD + j], A1[j * HD + c], acc);
                g_P2A1[rr * HD + c] = acc;
            }
            float acc = b1[c];
            for (int j = 0; j < HD; j++) acc = fmaf(bp2[j], A1[j * HD + c], acc);
            g_c1[c] = acc;
        }
    } else if (blk < SETUP_BLKS) {
        int n = blk - CIN - 1;    // 0..127
        if (c < HD)
            g_WoutPh[n * HD + c] = __float2half_rn(Wout[c * HD + n]);
    } else {
        int e = (blk - SETUP_BLKS) * 384 + c;
        if (e < CONV_ITEMS) {
            float4 v = ((const float4*)feat)[e];
            uint2 o;
            *(__half2*)&o.x = __floats2half2_rn(v.x, v.y);
            *(__half2*)&o.y = __floats2half2_rn(v.z, v.w);
            ((uint2*)g_feath)[e] = o;
        }
    }
}

// ---------------- fp16 mma GEMM -----------------------------------------------
// Tile 32(M) x 64(N), 128 thr (4 warps), warp computes 16x32.
// NCH <= 2: all chunks prefetched upfront into independent stages, single wait.
template <int KTOT, int LDA, int LDB, int LDC, bool HASBIAS, bool HALFOUT>
__global__ void __launch_bounds__(128) mma_gemm_kernel(const __half* __restrict__ A,
                                                       const __half* __restrict__ B,
                                                       const float* __restrict__ bias,
                                                       void* __restrict__ Cv) {
    constexpr int NCH = KTOT / 64;
    static_assert(NCH <= 2, "NCH must be 1 or 2");
    __shared__ __align__(16) char sA[2][4096];   // 32 rows x 64 halves (swizzled)
    __shared__ __align__(16) char sB[2][8192];   // 64 rows x 64 halves

    const int tid = threadIdx.x, wid = tid >> 5, lane = tid & 31;
    const int row0 = blockIdx.x * 32, col0 = blockIdx.y * 64;
    const int wm = (wid & 1) * 16, wn = (wid >> 1) * 32;
    const uint32_t sAb = smem_to_u32(sA), sBb = smem_to_u32(sB);

    float c[4][4];
#pragma unroll
    for (int nt = 0; nt < 4; nt++)
#pragma unroll
        for (int q = 0; q < 4; q++) c[nt][q] = 0.f;

    const uint32_t lrow = lane & 15;
    const uint32_t lcb  = (lane >> 4) * 16;
    const int lr0 = tid >> 3, lc0 = tid & 7;

    auto issue_load = [&](int ch, int st) {
#pragma unroll
        for (int u = 0; u < 2; u++) {
            int r = lr0 + u * 16;
            uint32_t off = SWZ((uint32_t)(r * 128 + lc0 * 16));
            CP_ASYNC16(sAb + st * 4096 + off,
                       A + (size_t)(row0 + r) * LDA + ch * 64 + lc0 * 8);
        }
#pragma unroll
        for (int u = 0; u < 4; u++) {
            int r = lr0 + u * 16;
            uint32_t off = SWZ((uint32_t)(r * 128 + lc0 * 16));
            CP_ASYNC16(sBb + st * 8192 + off,
                       B + (size_t)(col0 + r) * LDB + ch * 64 + lc0 * 8);
        }
        CP_COMMIT();
    };

    issue_load(0, 0);
    if (NCH == 2) issue_load(1, 1);
    CP_WAIT(0);
    __syncthreads();

#pragma unroll
    for (int ch = 0; ch < NCH; ch++) {
#pragma unroll
        for (int k16 = 0; k16 < 4; k16++) {
            uint32_t a[4], bf[2][4];
            {
                uint32_t b = SWZ((wm + lrow) * 128 + k16 * 32 + lcb);
                LDSM_X4(a[0], a[1], a[2], a[3], sAb + ch * 4096 + b);
            }
#pragma unroll
            for (int np = 0; np < 2; np++) {
                uint32_t b = SWZ((wn + np * 16 + lrow) * 128 + k16 * 32 + lcb);
                LDSM_X4(bf[np][0], bf[np][1], bf[np][2], bf[np][3], sBb + ch * 8192 + b);
            }
#pragma unroll
            for (int nt = 0; nt < 4; nt++)
                MMA_F16(c[nt], a, bf[nt >> 1][nt & 1], bf[nt >> 1][(nt & 1) + 2]);
        }
    }

    // epilogue
    {
        int r = row0 + wm + (lane >> 2);
#pragma unroll
        for (int nt = 0; nt < 4; nt++) {
            int cc = col0 + wn + nt * 8 + (lane & 3) * 2;
            if (HALFOUT) {
                __half* C = (__half*)Cv;
                *(__half2*)(C + (size_t)r * LDC + cc) =
                    __floats2half2_rn(c[nt][0], c[nt][1]);
                *(__half2*)(C + (size_t)(r + 8) * LDC + cc) =
                    __floats2half2_rn(c[nt][2], c[nt][3]);
            } else {
                float* C = (float*)Cv;
                float bx = 0.f, by = 0.f;
                if (HASBIAS) { bx = bias[cc]; by = bias[cc + 1]; }
                *(float2*)(C + (size_t)r * LDC + cc) =
                    make_float2(c[nt][0] + bx, c[nt][1] + by);
                *(float2*)(C + (size_t)(r + 8) * LDC + cc) =
                    make_float2(c[nt][2] + bx, c[nt][3] + by);
            }
        }
    }
}

// ---------------- fused attention kernel: one warp per point ----------------
// Logit layout after batched transpose-reduce:
//   lane holds logit(h, k) with h = ((lane&16)>>3)|(lane&1), j = (lane>>1)&7,
//   k = j (lk0) or j+8 (lk1). Head group = 8 lanes differing in bits 1..3.
__global__ void __launch_bounds__(128, 7) attn_kernel(const float* __restrict__ xyzs,
                                                      const int* __restrict__ kg,
                                                      const float* __restrict__ A2,
                                                      const float* __restrict__ P1,
                                                      const float* __restrict__ bp1,
                                                      const float* __restrict__ P2,
                                                      const float* __restrict__ bp2) {
    const unsigned FULL = 0xffffffffu;
    const int warp = threadIdx.x >> 5;
    const int lane = threadIdx.x & 31;
    const int pt   = blockIdx.x * 4 + warp;
    const int bN   = pt & ~(NN - 1);
    const int c0   = lane * 4;

    // ---- upfront: per-lane neighbor prep (lane l -> neighbor l&15) ----
    int rowoff_l;
    float t0_l, t1_l, t2_l;
    __half2 t01h_l, t2h_l;
    {
        int idx = kg[(size_t)pt * NK + (lane & 15)];
        rowoff_l = (bN + idx) * NCAT;
        const float* nx = xyzs + (size_t)(bN + idx) * 3;
        float cx = xyzs[(size_t)pt * 3 + 0];
        float cy = xyzs[(size_t)pt * 3 + 1];
        float cz = xyzs[(size_t)pt * 3 + 2];
        float rx = cx - nx[0], ry = cy - nx[1], rz = cz - nx[2];
        t0_l = fmaxf(fmaf(rx, P1[0], fmaf(ry, P1[3], fmaf(rz, P1[6], bp1[0]))), 0.f);
        t1_l = fmaxf(fmaf(rx, P1[1], fmaf(ry, P1[4], fmaf(rz, P1[7], bp1[1]))), 0.f);
        t2_l = fmaxf(fmaf(rx, P1[2], fmaf(ry, P1[5], fmaf(rz, P1[8], bp1[2]))), 0.f);
        t01h_l = __floats2half2_rn(t0_l, t1_l);
        t2h_l  = __float2half2_rn(t2_l);
    }

    // per-lane channel constants (packed half2)
    __half2 hb0, hb1;
    __half2 hp[3][2];
    __half2 a01[4], a23[4];
    {
        uint2 qa = *(const uint2*)(g_QKVh + (size_t)pt * NCAT + c0);
        float4 c1 = *(const float4*)(g_c1 + c0);
        hb0 = __hadd2(*(__half2*)&qa.x, __floats2half2_rn(c1.x, c1.y));
        hb1 = __hadd2(*(__half2*)&qa.y, __floats2half2_rn(c1.z, c1.w));
#pragma unroll
        for (int r = 0; r < 3; r++) {
            float4 v = *(const float4*)(g_P2A1 + r * HD + c0);
            hp[r][0] = __floats2half2_rn(v.x, v.y);
            hp[r][1] = __floats2half2_rn(v.z, v.w);
        }
#pragma unroll
        for (int i = 0; i < 4; i++) {
            float4 a2v = *(const float4*)(A2 + (c0 + i) * 4);
            a01[i] = __floats2half2_rn(a2v.x, a2v.y);
            a23[i] = __floats2half2_rn(a2v.z, a2v.w);
        }
    }
    const __half2 z2 = __float2half2_rn(0.f);
    const bool hi = (lane & 16) != 0;
    const bool b3 = (lane & 8) != 0;
    const bool b2 = (lane & 4) != 0;
    const bool b1b = (lane & 2) != 0;

    float lk0 = 0.f, lk1 = 0.f;

    // ---- pass 1: two batches of 8 neighbors, batched transpose-reduce ----
#pragma unroll
    for (int kb = 0; kb < 2; kb++) {
        __half2 u[8];
#pragma unroll
        for (int j = 0; j < 8; j++) {
            const int k = kb * 8 + j;
            int rowoff = __shfl_sync(FULL, rowoff_l, k);
            __half2 t01 = shfl_h2(t01h_l, k);
            __half2 tb2 = shfl_h2(t2h_l, k);
            __half2 tb0 = __low2half2(t01);
            __half2 tb1 = __high2half2(t01);
            uint2 kau = *(const uint2*)(g_QKVh + rowoff + HD + c0);
            __half2 h0 = __hsub2(hb0, *(__half2*)&kau.x);
            __half2 h1 = __hsub2(hb1, *(__half2*)&kau.y);
            h0 = __hfma2(tb0, hp[0][0], h0);
            h0 = __hfma2(tb1, hp[1][0], h0);
            h0 = __hfma2(tb2, hp[2][0], h0);
            h1 = __hfma2(tb0, hp[0][1], h1);
            h1 = __hfma2(tb1, hp[1][1], h1);
            h1 = __hfma2(tb2, hp[2][1], h1);
            __half2 r0 = __hmax2(h0, z2);
            __half2 r1 = __hmax2(h1, z2);
            __half2 q01 = z2, q23 = z2, b;
            b = __low2half2(r0);  q01 = __hfma2(b, a01[0], q01); q23 = __hfma2(b, a23[0], q23);
            b = __high2half2(r0); q01 = __hfma2(b, a01[1], q01); q23 = __hfma2(b, a23[1], q23);
            b = __low2half2(r1);  q01 = __hfma2(b, a01[2], q01); q23 = __hfma2(b, a23[2], q23);
            b = __high2half2(r1); q01 = __hfma2(b, a01[3], q01); q23 = __hfma2(b, a23[3], q23);
            // round 1 (xor 16): merge head tracks; lo lanes keep track01, hi track23
            __half2 sel = hi ? q01 : q23;
            __half2 keep = hi ? q23 : q01;
            u[j] = __hadd2(keep, shfl_xor_h2(sel, 16));
        }
        // round 2 (xor 8): lane bit3 = j bit2
        __half2 w[4];
#pragma unroll
        for (int i = 0; i < 4; i++) {
            __half2 sel = b3 ? u[i] : u[i + 4];
            __half2 keep = b3 ? u[i + 4] : u[i];
            w[i] = __hadd2(keep, shfl_xor_h2(sel, 8));
        }
        // round 3 (xor 4): lane bit2 = j bit1
        __half2 x[2];
#pragma unroll
        for (int i = 0; i < 2; i++) {
            __half2 sel = b2 ? w[i] : w[i + 2];
            __half2 keep = b2 ? w[i + 2] : w[i];
            x[i] = __hadd2(keep, shfl_xor_h2(sel, 4));
        }
        // round 4 (xor 2): lane bit1 = j bit0
        __half2 sel = b1b ? x[0] : x[1];
        __half2 keep = b1b ? x[1] : x[0];
        __half2 y = __hadd2(keep, shfl_xor_h2(sel, 2));
        // round 5 (xor 1): final pair sum (both lanes hold total)
        __half2 z = __hadd2(y, shfl_xor_h2(y, 1));
        float L = (lane & 1) ? __high2float(z) : __low2float(z);
        if (kb == 0) lk0 = L; else lk1 = L;
    }

    // ---- softmax: head group lanes differ in bits 1..3 (xor 2,4,8) ----
    float mx = fmaxf(lk0, lk1);
    mx = fmaxf(mx, __shfl_xor_sync(FULL, mx, 2));
    mx = fmaxf(mx, __shfl_xor_sync(FULL, mx, 4));
    mx = fmaxf(mx, __shfl_xor_sync(FULL, mx, 8));
    float e0 = __expf(lk0 - mx), e1 = __expf(lk1 - mx);
    float s = e0 + e1;
    s += __shfl_xor_sync(FULL, s, 2);
    s += __shfl_xor_sync(FULL, s, 4);
    s += __shfl_xor_sync(FULL, s, 8);
    float inv = __fdividef(1.f, s);
    float a0 = e0 * inv, a1 = e1 * inv;   // attn(h(lane), j(lane)) and (.., j+8)

    // ---- factored pe reduction: S_r(h) = sum_k attn(h,k)*t_r(k) ----
    float S0, S1, S2, S3;
    {
        int j = (lane >> 1) & 7;
        float ua = __shfl_sync(FULL, t0_l, j);
        float ub = __shfl_sync(FULL, t0_l, j + 8);
        S0 = a0 * ua + a1 * ub;
        ua = __shfl_sync(FULL, t1_l, j);
        ub = __shfl_sync(FULL, t1_l, j + 8);
        S1 = a0 * ua + a1 * ub;
        ua = __shfl_sync(FULL, t2_l, j);
        ub = __shfl_sync(FULL, t2_l, j + 8);
        S2 = a0 * ua + a1 * ub;
        S3 = a0 + a1;
#pragma unroll
        for (int m = 2; m <= 8; m <<= 1) {
            S0 += __shfl_xor_sync(FULL, S0, m);
            S1 += __shfl_xor_sync(FULL, S1, m);
            S2 += __shfl_xor_sync(FULL, S2, m);
            S3 += __shfl_xor_sync(FULL, S3, m);
        }
    }
    // broadcast S(h) to consumer lanes (head = lane>>3); producer j=0 lane:
    const int hb = (((lane >> 3) & 2) << 3) | ((lane >> 3) & 1);
    S0 = __shfl_sync(FULL, S0, hb);
    S1 = __shfl_sync(FULL, S1, hb);
    S2 = __shfl_sync(FULL, S2, hb);
    S3 = __shfl_sync(FULL, S3, hb);

    float accv[4];
    {
        float4 v0 = *(const float4*)(P2 + 0 * HD + c0);
        float4 v1 = *(const float4*)(P2 + 1 * HD + c0);
        float4 v2 = *(const float4*)(P2 + 2 * HD + c0);
        float4 vb = *(const float4*)(bp2 + c0);
        accv[0] = fmaf(S0, v0.x, fmaf(S1, v1.x, fmaf(S2, v2.x, S3 * vb.x)));
        accv[1] = fmaf(S0, v0.y, fmaf(S1, v1.y, fmaf(S2, v2.y, S3 * vb.y)));
        accv[2] = fmaf(S0, v0.z, fmaf(S1, v1.z, fmaf(S2, v2.z, S3 * vb.z)));
        accv[3] = fmaf(S0, v0.w, fmaf(S1, v1.w, fmaf(S2, v2.w, S3 * vb.w)));
    }

    // ---- pass 2: weighted V reduce ----
#pragma unroll
    for (int k = 0; k < NK; k++) {
        int src = hb | ((k & 7) << 1);
        float asel = (k < 8) ? a0 : a1;
        float aw = __shfl_sync(FULL, asel, src);
        int rowoff = __shfl_sync(FULL, rowoff_l, k);
        float4 vv = ldh4(g_QKVh + rowoff + 2 * HD + c0);
        accv[0] = fmaf(aw, vv.x, accv[0]);
        accv[1] = fmaf(aw, vv.y, accv[1]);
        accv[2] = fmaf(aw, vv.z, accv[2]);
        accv[3] = fmaf(aw, vv.w, accv[3]);
    }

    {
        uint2 o;
        *(__half2*)&o.x = __floats2half2_rn(accv[0], accv[1]);
        *(__half2*)&o.y = __floats2half2_rn(accv[2], accv[3]);
        *(uint2*)(g_fusedh + (size_t)pt * HD + c0) = o;
    }
}

// ======================= launch =============================================
extern "C" void kernel_launch(void* const* d_in, const int* in_sizes, int n_in,
                              void* d_out, int out_size) {
    const float* xyzs     = (const float*)d_in[0];
    const float* features = (const float*)d_in[1];
    const int*   kg       = (const int*)d_in[2];
    const float* Wk   = (const float*)d_in[3];
    const float* Wv   = (const float*)d_in[4];
    const float* Wq   = (const float*)d_in[5];
    const float* A1   = (const float*)d_in[6];
    const float* b1   = (const float*)d_in[7];
    const float* A2   = (const float*)d_in[8];
    const float* P1   = (const float*)d_in[10];
    const float* bp1  = (const float*)d_in[11];
    const float* P2   = (const float*)d_in[12];
    const float* bp2  = (const float*)d_in[13];
    const float* Wout = (const float*)d_in[14];
    const float* bout = (const float*)d_in[15];
    float* out = (float*)d_out;

    __half *pQKVh, *pFeath, *pWcatPh, *pWoutPh, *pFusedh;
    cudaGetSymbolAddress((void**)&pQKVh,   g_QKVh);
    cudaGetSymbolAddress((void**)&pFeath,  g_feath);
    cudaGetSymbolAddress((void**)&pWcatPh, g_WcatPh);
    cudaGetSymbolAddress((void**)&pWoutPh, g_WoutPh);
    cudaGetSymbolAddress((void**)&pFusedh, g_fusedh);

    const int conv_blks = (CONV_ITEMS + 383) / 384;
    setup_kernel<<<SETUP_BLKS + conv_blks, 384>>>(Wq, Wk, Wv, A1, P2, b1, bp2,
                                                  Wout, features);

    // QKV: [16384 x 64] @ [384 x 64]^T -> fp16 [16384 x 384]   (3072 blocks)
    mma_gemm_kernel<CIN, CIN, CIN, NCAT, false, true>
        <<<dim3(NPTS / 32, NCAT / 64), 128>>>(pFeath, pWcatPh, nullptr, pQKVh);

    attn_kernel<<<NPTS / 4, 128>>>(xyzs, kg, A2, P1, bp1, P2, bp2);

    // out: [16384 x 128] @ [128 x 128]^T + bout -> fp32        (1024 blocks)
    mma_gemm_kernel<HD, HD, HD, COUT, true, false>
        <<<dim3(NPTS / 32, COUT / 64), 128>>>(pFusedh, pWoutPh, bout, out);
}

// round 14
// speedup vs baseline: 1.0337x; 1.0337x over previous
#include <cuda_runtime.h>
#include <cuda_fp16.h>
#include <cstdint>

#define NB   2
#define NN   8192
#define NK   16
#define HD   128
#define CIN  64
#define COUT 128
#define NPTS (NB * NN)   // 16384
#define NCAT 384         // QA|KA|V concatenated

// ---------------- helpers ----------------------------------------------------
__device__ __forceinline__ uint32_t smem_to_u32(const void* p) {
    uint32_t a;
    asm("{ .reg .u64 t; cvta.to.shared.u64 t, %1; cvt.u32.u64 %0, t; }"
        : "=r"(a) : "l"(p));
    return a;
}
#define LDSM_X4(r0, r1, r2, r3, addr) \
    asm volatile("ldmatrix.sync.aligned.m8n8.x4.shared.b16 {%0,%1,%2,%3}, [%4];" \
                 : "=r"(r0), "=r"(r1), "=r"(r2), "=r"(r3) : "r"(addr))
#define MMA_F16(c, a, b0, b1) \
    asm volatile("mma.sync.aligned.m16n8k16.row.col.f32.f16.f16.f32 " \
                 "{%0,%1,%2,%3}, {%4,%5,%6,%7}, {%8,%9}, {%0,%1,%2,%3};" \
                 : "+f"((c)[0]), "+f"((c)[1]), "+f"((c)[2]), "+f"((c)[3]) \
                 : "r"((a)[0]), "r"((a)[1]), "r"((a)[2]), "r"((a)[3]), \
                   "r"(b0), "r"(b1))
#define CP_ASYNC16(dst, src) \
    asm volatile("cp.async.cg.shared.global [%0], [%1], 16;" \
                 :: "r"(dst), "l"(src) : "memory")
#define CP_COMMIT() asm volatile("cp.async.commit_group;" ::: "memory")
#define CP_WAIT(n)  asm volatile("cp.async.wait_group %0;" :: "n"(n) : "memory")
#define SWZ(b) ((b) ^ (((b) >> 3) & 0x70))

__device__ __forceinline__ float4 ldh4(const __half* p) {
    uint2 u = *(const uint2*)p;
    float2 fa = __half22float2(*(__half2*)&u.x);
    float2 fb = __half22float2(*(__half2*)&u.y);
    return make_float4(fa.x, fa.y, fb.x, fb.y);
}
__device__ __forceinline__ __half2 shfl_h2(__half2 v, int src) {
    uint32_t u = *(uint32_t*)&v;
    u = __shfl_sync(0xffffffffu, u, src);
    return *(__half2*)&u;
}
__device__ __forceinline__ __half2 shfl_xor_h2(__half2 v, int m) {
    uint32_t u = *(uint32_t*)&v;
    u = __shfl_xor_sync(0xffffffffu, u, m);
    return *(__half2*)&u;
}

// ---------------- scratch globals --------------------------------------------
__device__ float g_P2A1[3 * HD];
__device__ float g_c1[HD];
__device__ __align__(16) __half g_QKVh[NPTS * NCAT];       // fp16 [QA|KA|V]
__device__ __align__(16) __half g_feath[NPTS * CIN];       // fp16 features
__device__ __align__(16) __half g_WcatPh[NCAT * CIN];      // fp16 [n][k] folded
__device__ __align__(16) __half g_WoutPh[HD * HD];         // fp16 [n][k]
__device__ __align__(16) __half g_fusedh[NPTS * HD];       // fp16 fused

// ---------------- setup + feature convert (merged, one launch) ---------------
#define SETUP_BLKS (CIN + 1 + HD)          // 193
#define CONV_ITEMS (NPTS * CIN / 4)        // 262144
__global__ void setup_kernel(const float* __restrict__ Wq, const float* __restrict__ Wk,
                             const float* __restrict__ Wv, const float* __restrict__ A1,
                             const float* __restrict__ P2, const float* __restrict__ b1,
                             const float* __restrict__ bp2, const float* __restrict__ Wout,
                             const float* __restrict__ feat) {
    int c = threadIdx.x;          // 0..383
    int blk = blockIdx.x;
    if (blk < CIN) {
        int r = blk;
        float acc;
        if (c < 2 * HD) {
            const float* w = (c < HD) ? (Wq + r * HD) : (Wk + r * HD);
            int cc = c & (HD - 1);
            float a0 = 0.f, a1 = 0.f, a2 = 0.f, a3 = 0.f;
#pragma unroll 8
            for (int j = 0; j < HD; j += 4) {
                a0 = fmaf(w[j],     A1[j * HD + cc],       a0);
                a1 = fmaf(w[j + 1], A1[(j + 1) * HD + cc], a1);
                a2 = fmaf(w[j + 2], A1[(j + 2) * HD + cc], a2);
                a3 = fmaf(w[j + 3], A1[(j + 3) * HD + cc], a3);
            }
            acc = (a0 + a1) + (a2 + a3);
        } else {
            acc = Wv[r * HD + (c - 2 * HD)];
        }
        g_WcatPh[c * CIN + r] = __float2half_rn(acc);
    } else if (blk == CIN) {
        if (c < HD) {
            for (int rr = 0; rr < 3; rr++) {
                float a0 = 0.f, a1 = 0.f, a2 = 0.f, a3 = 0.f;
#pragma unroll 8
                for (int j = 0; j < HD; j += 4) {
                    a0 = fmaf(P2[rr * HD + j],     A1[j * HD + c],       a0);
                    a1 = fmaf(P2[rr * HD + j + 1], A1[(j + 1) * HD + c], a1);
                    a2 = fmaf(P2[rr * HD + j + 2], A1[(j + 2) * HD + c], a2);
                    a3 = fmaf(P2[rr * HD + j + 3], A1[(j + 3) * HD + c], a3);
                }
                g_P2A1[rr * HD + c] = (a0 + a1) + (a2 + a3);
            }
            float a0 = b1[c], a1 = 0.f, a2 = 0.f, a3 = 0.f;
#pragma unroll 8
            for (int j = 0; j < HD; j += 4) {
                a0 = fmaf(bp2[j],     A1[j * HD + c],       a0);
                a1 = fmaf(bp2[j + 1], A1[(j + 1) * HD + c], a1);
                a2 = fmaf(bp2[j + 2], A1[(j + 2) * HD + c], a2);
                a3 = fmaf(bp2[j + 3], A1[(j + 3) * HD + c], a3);
            }
            g_c1[c] = (a0 + a1) + (a2 + a3);
        }
    } else if (blk < SETUP_BLKS) {
        int n = blk - CIN - 1;    // 0..127
        if (c < HD)
            g_WoutPh[n * HD + c] = __float2half_rn(Wout[c * HD + n]);
    } else {
        int e = (blk - SETUP_BLKS) * 384 + c;
        if (e < CONV_ITEMS) {
            float4 v = ((const float4*)feat)[e];
            uint2 o;
            *(__half2*)&o.x = __floats2half2_rn(v.x, v.y);
            *(__half2*)&o.y = __floats2half2_rn(v.z, v.w);
            ((uint2*)g_feath)[e] = o;
        }
    }
}

// ---------------- fp16 mma GEMM -----------------------------------------------
// Tile 32(M) x 32(N), 128 thr (4 warps), warp computes 16x16 (2 MMA/k16).
// NCH <= 2: all chunks prefetched upfront into independent stages, single wait.
template <int KTOT, int LDA, int LDB, int LDC, bool HASBIAS, bool HALFOUT>
__global__ void __launch_bounds__(128) mma_gemm_kernel(const __half* __restrict__ A,
                                                       const __half* __restrict__ B,
                                                       const float* __restrict__ bias,
                                                       void* __restrict__ Cv) {
    constexpr int NCH = KTOT / 64;
    static_assert(NCH <= 2, "NCH must be 1 or 2");
    __shared__ __align__(16) char sA[2][4096];   // 32 rows x 64 halves (swizzled)
    __shared__ __align__(16) char sB[2][4096];   // 32 rows x 64 halves

    const int tid = threadIdx.x, wid = tid >> 5, lane = tid & 31;
    const int row0 = blockIdx.x * 32, col0 = blockIdx.y * 32;
    const int wm = (wid & 1) * 16, wn = (wid >> 1) * 16;
    const uint32_t sAb = smem_to_u32(sA), sBb = smem_to_u32(sB);

    float c[2][4];
#pragma unroll
    for (int nt = 0; nt < 2; nt++)
#pragma unroll
        for (int q = 0; q < 4; q++) c[nt][q] = 0.f;

    const uint32_t lrow = lane & 15;
    const uint32_t lcb  = (lane >> 4) * 16;
    const int lr0 = tid >> 3, lc0 = tid & 7;

    auto issue_load = [&](int ch, int st) {
#pragma unroll
        for (int u = 0; u < 2; u++) {
            int r = lr0 + u * 16;
            uint32_t off = SWZ((uint32_t)(r * 128 + lc0 * 16));
            CP_ASYNC16(sAb + st * 4096 + off,
                       A + (size_t)(row0 + r) * LDA + ch * 64 + lc0 * 8);
            CP_ASYNC16(sBb + st * 4096 + off,
                       B + (size_t)(col0 + r) * LDB + ch * 64 + lc0 * 8);
        }
        CP_COMMIT();
    };

    issue_load(0, 0);
    if (NCH == 2) issue_load(1, 1);
    CP_WAIT(0);
    __syncthreads();

#pragma unroll
    for (int ch = 0; ch < NCH; ch++) {
#pragma unroll
        for (int k16 = 0; k16 < 4; k16++) {
            uint32_t a[4], bf[4];
            {
                uint32_t b = SWZ((wm + lrow) * 128 + k16 * 32 + lcb);
                LDSM_X4(a[0], a[1], a[2], a[3], sAb + ch * 4096 + b);
            }
            {
                uint32_t b = SWZ((wn + lrow) * 128 + k16 * 32 + lcb);
                LDSM_X4(bf[0], bf[1], bf[2], bf[3], sBb + ch * 4096 + b);
            }
            MMA_F16(c[0], a, bf[0], bf[2]);
            MMA_F16(c[1], a, bf[1], bf[3]);
        }
    }

    // epilogue
    {
        int r = row0 + wm + (lane >> 2);
#pragma unroll
        for (int nt = 0; nt < 2; nt++) {
            int cc = col0 + wn + nt * 8 + (lane & 3) * 2;
            if (HALFOUT) {
                __half* C = (__half*)Cv;
                *(__half2*)(C + (size_t)r * LDC + cc) =
                    __floats2half2_rn(c[nt][0], c[nt][1]);
                *(__half2*)(C + (size_t)(r + 8) * LDC + cc) =
                    __floats2half2_rn(c[nt][2], c[nt][3]);
            } else {
                float* C = (float*)Cv;
                float bx = 0.f, by = 0.f;
                if (HASBIAS) { bx = bias[cc]; by = bias[cc + 1]; }
                *(float2*)(C + (size_t)r * LDC + cc) =
                    make_float2(c[nt][0] + bx, c[nt][1] + by);
                *(float2*)(C + (size_t)(r + 8) * LDC + cc) =
                    make_float2(c[nt][2] + bx, c[nt][3] + by);
            }
        }
    }
}

// ---------------- fused attention kernel: one warp per point (R12 version) ---
__global__ void __launch_bounds__(128, 7) attn_kernel(const float* __restrict__ xyzs,
                                                      const int* __restrict__ kg,
                                                      const float* __restrict__ A2,
                                                      const float* __restrict__ P1,
                                                      const float* __restrict__ bp1,
                                                      const float* __restrict__ P2,
                                                      const float* __restrict__ bp2) {
    const unsigned FULL = 0xffffffffu;
    const int warp = threadIdx.x >> 5;
    const int lane = threadIdx.x & 31;
    const int pt   = blockIdx.x * 4 + warp;
    const int bN   = pt & ~(NN - 1);
    const int c0   = lane * 4;

    // ---- upfront: per-lane neighbor prep (lane l -> neighbor l&15) ----
    int rowoff_l;
    float t0_l, t1_l, t2_l;
    __half2 t01h_l, t2h_l;
    {
        int idx = kg[(size_t)pt * NK + (lane & 15)];
        rowoff_l = (bN + idx) * NCAT;
        const float* nx = xyzs + (size_t)(bN + idx) * 3;
        float cx = xyzs[(size_t)pt * 3 + 0];
        float cy = xyzs[(size_t)pt * 3 + 1];
        float cz = xyzs[(size_t)pt * 3 + 2];
        float rx = cx - nx[0], ry = cy - nx[1], rz = cz - nx[2];
        t0_l = fmaxf(fmaf(rx, P1[0], fmaf(ry, P1[3], fmaf(rz, P1[6], bp1[0]))), 0.f);
        t1_l = fmaxf(fmaf(rx, P1[1], fmaf(ry, P1[4], fmaf(rz, P1[7], bp1[1]))), 0.f);
        t2_l = fmaxf(fmaf(rx, P1[2], fmaf(ry, P1[5], fmaf(rz, P1[8], bp1[2]))), 0.f);
        t01h_l = __floats2half2_rn(t0_l, t1_l);
        t2h_l  = __float2half2_rn(t2_l);
    }

    // per-lane channel constants (packed half2)
    __half2 hb0, hb1;
    __half2 hp[3][2];
    __half2 a01[4], a23[4];
    {
        uint2 qa = *(const uint2*)(g_QKVh + (size_t)pt * NCAT + c0);
        float4 c1 = *(const float4*)(g_c1 + c0);
        hb0 = __hadd2(*(__half2*)&qa.x, __floats2half2_rn(c1.x, c1.y));
        hb1 = __hadd2(*(__half2*)&qa.y, __floats2half2_rn(c1.z, c1.w));
#pragma unroll
        for (int r = 0; r < 3; r++) {
            float4 v = *(const float4*)(g_P2A1 + r * HD + c0);
            hp[r][0] = __floats2half2_rn(v.x, v.y);
            hp[r][1] = __floats2half2_rn(v.z, v.w);
        }
#pragma unroll
        for (int i = 0; i < 4; i++) {
            float4 a2v = *(const float4*)(A2 + (c0 + i) * 4);
            a01[i] = __floats2half2_rn(a2v.x, a2v.y);
            a23[i] = __floats2half2_rn(a2v.z, a2v.w);
        }
    }
    const __half2 z2 = __float2half2_rn(0.f);
    const bool hi = (lane & 16) != 0;

    __half2 lku0 = z2, lku1 = z2;   // packed logits; extract after loop

    // ---- pass 1: per-neighbor logits (half2 math) ----
#pragma unroll
    for (int k = 0; k < NK; k++) {
        int rowoff = __shfl_sync(FULL, rowoff_l, k);
        __half2 t01 = shfl_h2(t01h_l, k);
        __half2 tb2 = shfl_h2(t2h_l, k);
        __half2 tb0 = __low2half2(t01);
        __half2 tb1 = __high2half2(t01);
        uint2 kau = *(const uint2*)(g_QKVh + rowoff + HD + c0);
        __half2 h0 = __hsub2(hb0, *(__half2*)&kau.x);
        __half2 h1 = __hsub2(hb1, *(__half2*)&kau.y);
        h0 = __hfma2(tb0, hp[0][0], h0);
        h0 = __hfma2(tb1, hp[1][0], h0);
        h0 = __hfma2(tb2, hp[2][0], h0);
        h1 = __hfma2(tb0, hp[0][1], h1);
        h1 = __hfma2(tb1, hp[1][1], h1);
        h1 = __hfma2(tb2, hp[2][1], h1);
        __half2 r0 = __hmax2(h0, z2);
        __half2 r1 = __hmax2(h1, z2);
        __half2 q01 = z2, q23 = z2, b;
        b = __low2half2(r0);  q01 = __hfma2(b, a01[0], q01); q23 = __hfma2(b, a23[0], q23);
        b = __high2half2(r0); q01 = __hfma2(b, a01[1], q01); q23 = __hfma2(b, a23[1], q23);
        b = __low2half2(r1);  q01 = __hfma2(b, a01[2], q01); q23 = __hfma2(b, a23[2], q23);
        b = __high2half2(r1); q01 = __hfma2(b, a01[3], q01); q23 = __hfma2(b, a23[3], q23);
        __half2 sel = hi ? q01 : q23;
        __half2 oth = hi ? q23 : q01;
        __half2 u = __hadd2(oth, shfl_xor_h2(sel, 16));
        u = __hadd2(u, shfl_xor_h2(u, 8));
        u = __hadd2(u, shfl_xor_h2(u, 4));
        u = __hadd2(u, shfl_xor_h2(u, 2));
        u = __hadd2(u, shfl_xor_h2(u, 1));
        if ((lane & 7) == (k & 7)) {
            if (k < 8) lku0 = u; else lku1 = u;
        }
    }
    // extract this lane's head (lane&8 -> high half)
    float lk0 = (lane & 8) ? __high2float(lku0) : __low2float(lku0);
    float lk1 = (lane & 8) ? __high2float(lku1) : __low2float(lku1);

    // ---- softmax: head h in 8-lane group [8h, 8h+7], 2 logits/lane ----
    float mx = fmaxf(lk0, lk1);
    mx = fmaxf(mx, __shfl_xor_sync(FULL, mx, 4));
    mx = fmaxf(mx, __shfl_xor_sync(FULL, mx, 2));
    mx = fmaxf(mx, __shfl_xor_sync(FULL, mx, 1));
    float e0 = __expf(lk0 - mx), e1 = __expf(lk1 - mx);
    float s = e0 + e1;
    s += __shfl_xor_sync(FULL, s, 4);
    s += __shfl_xor_sync(FULL, s, 2);
    s += __shfl_xor_sync(FULL, s, 1);
    float inv = __fdividef(1.f, s);
    float a0 = e0 * inv, a1 = e1 * inv;

    // ---- factored pe reduction ----
    float S0, S1, S2, S3;
    {
        int kk = lane & 7;
        float ua = __shfl_sync(FULL, t0_l, kk);
        float ub = __shfl_sync(FULL, t0_l, kk + 8);
        S0 = a0 * ua + a1 * ub;
        ua = __shfl_sync(FULL, t1_l, kk);
        ub = __shfl_sync(FULL, t1_l, kk + 8);
        S1 = a0 * ua + a1 * ub;
        ua = __shfl_sync(FULL, t2_l, kk);
        ub = __shfl_sync(FULL, t2_l, kk + 8);
        S2 = a0 * ua + a1 * ub;
        S3 = a0 + a1;
#pragma unroll
        for (int m = 4; m >= 1; m >>= 1) {
            S0 += __shfl_xor_sync(FULL, S0, m);
            S1 += __shfl_xor_sync(FULL, S1, m);
            S2 += __shfl_xor_sync(FULL, S2, m);
            S3 += __shfl_xor_sync(FULL, S3, m);
        }
    }

    float accv[4];
    {
        float4 v0 = *(const float4*)(P2 + 0 * HD + c0);
        float4 v1 = *(const float4*)(P2 + 1 * HD + c0);
        float4 v2 = *(const float4*)(P2 + 2 * HD + c0);
        float4 vb = *(const float4*)(bp2 + c0);
        accv[0] = fmaf(S0, v0.x, fmaf(S1, v1.x, fmaf(S2, v2.x, S3 * vb.x)));
        accv[1] = fmaf(S0, v0.y, fmaf(S1, v1.y, fmaf(S2, v2.y, S3 * vb.y)));
        accv[2] = fmaf(S0, v0.z, fmaf(S1, v1.z, fmaf(S2, v2.z, S3 * vb.z)));
        accv[3] = fmaf(S0, v0.w, fmaf(S1, v1.w, fmaf(S2, v2.w, S3 * vb.w)));
    }

    const int hsrc = lane & 24;

    // ---- pass 2: weighted V reduce ----
#pragma unroll
    for (int k = 0; k < NK; k++) {
        float asel = (k < 8) ? a0 : a1;
        float aw = __shfl_sync(FULL, asel, hsrc | (k & 7));
        int rowoff = __shfl_sync(FULL, rowoff_l, k);
        float4 vv = ldh4(g_QKVh + rowoff + 2 * HD + c0);
        accv[0] = fmaf(aw, vv.x, accv[0]);
        accv[1] = fmaf(aw, vv.y, accv[1]);
        accv[2] = fmaf(aw, vv.z, accv[2]);
        accv[3] = fmaf(aw, vv.w, accv[3]);
    }

    {
        uint2 o;
        *(__half2*)&o.x = __floats2half2_rn(accv[0], accv[1]);
        *(__half2*)&o.y = __floats2half2_rn(accv[2], accv[3]);
        *(uint2*)(g_fusedh + (size_t)pt * HD + c0) = o;
    }
}

// ======================= launch =============================================
extern "C" void kernel_launch(void* const* d_in, const int* in_sizes, int n_in,
                              void* d_out, int out_size) {
    const float* xyzs     = (const float*)d_in[0];
    const float* features = (const float*)d_in[1];
    const int*   kg       = (const int*)d_in[2];
    const float* Wk   = (const float*)d_in[3];
    const float* Wv   = (const float*)d_in[4];
    const float* Wq   = (const float*)d_in[5];
    const float* A1   = (const float*)d_in[6];
    const float* b1   = (const float*)d_in[7];
    const float* A2   = (const float*)d_in[8];
    const float* P1   = (const float*)d_in[10];
    const float* bp1  = (const float*)d_in[11];
    const float* P2   = (const float*)d_in[12];
    const float* bp2  = (const float*)d_in[13];
    const float* Wout = (const float*)d_in[14];
    const float* bout = (const float*)d_in[15];
    float* out = (float*)d_out;

    __half *pQKVh, *pFeath, *pWcatPh, *pWoutPh, *pFusedh;
    cudaGetSymbolAddress((void**)&pQKVh,   g_QKVh);
    cudaGetSymbolAddress((void**)&pFeath,  g_feath);
    cudaGetSymbolAddress((void**)&pWcatPh, g_WcatPh);
    cudaGetSymbolAddress((void**)&pWoutPh, g_WoutPh);
    cudaGetSymbolAddress((void**)&pFusedh, g_fusedh);

    const int conv_blks = (CONV_ITEMS + 383) / 384;
    setup_kernel<<<SETUP_BLKS + conv_blks, 384>>>(Wq, Wk, Wv, A1, P2, b1, bp2,
                                                  Wout, features);

    // QKV: [16384 x 64] @ [384 x 64]^T -> fp16 [16384 x 384]   (6144 blocks)
    mma_gemm_kernel<CIN, CIN, CIN, NCAT, false, true>
        <<<dim3(NPTS / 32, NCAT / 32), 128>>>(pFeath, pWcatPh, nullptr, pQKVh);

    attn_kernel<<<NPTS / 4, 128>>>(xyzs, kg, A2, P1, bp1, P2, bp2);

    // out: [16384 x 128] @ [128 x 128]^T + bout -> fp32        (2048 blocks)
    mma_gemm_kernel<HD, HD, HD, COUT, true, false>
        <<<dim3(NPTS / 32, COUT / 32), 128>>>(pFusedh, pWoutPh, bout, out);
}

// round 15
// speedup vs baseline: 1.0838x; 1.0485x over previous
#include <cuda_runtime.h>
#include <cuda_fp16.h>
#include <cstdint>

#define NB   2
#define NN   8192
#define NK   16
#define HD   128
#define CIN  64
#define COUT 128
#define NPTS (NB * NN)   // 16384
#define NCAT 384         // QA|KA|V concatenated

// ---------------- helpers ----------------------------------------------------
__device__ __forceinline__ uint32_t smem_to_u32(const void* p) {
    uint32_t a;
    asm("{ .reg .u64 t; cvta.to.shared.u64 t, %1; cvt.u32.u64 %0, t; }"
        : "=r"(a) : "l"(p));
    return a;
}
#define LDSM_X4(r0, r1, r2, r3, addr) \
    asm volatile("ldmatrix.sync.aligned.m8n8.x4.shared.b16 {%0,%1,%2,%3}, [%4];" \
                 : "=r"(r0), "=r"(r1), "=r"(r2), "=r"(r3) : "r"(addr))
#define MMA_F16(c, a, b0, b1) \
    asm volatile("mma.sync.aligned.m16n8k16.row.col.f32.f16.f16.f32 " \
                 "{%0,%1,%2,%3}, {%4,%5,%6,%7}, {%8,%9}, {%0,%1,%2,%3};" \
                 : "+f"((c)[0]), "+f"((c)[1]), "+f"((c)[2]), "+f"((c)[3]) \
                 : "r"((a)[0]), "r"((a)[1]), "r"((a)[2]), "r"((a)[3]), \
                   "r"(b0), "r"(b1))
#define CP_ASYNC16(dst, src) \
    asm volatile("cp.async.cg.shared.global [%0], [%1], 16;" \
                 :: "r"(dst), "l"(src) : "memory")
#define CP_COMMIT() asm volatile("cp.async.commit_group;" ::: "memory")
#define CP_WAIT(n)  asm volatile("cp.async.wait_group %0;" :: "n"(n) : "memory")
#define SWZ(b) ((b) ^ (((b) >> 3) & 0x70))

__device__ __forceinline__ float4 ldh4(const __half* p) {
    uint2 u = *(const uint2*)p;
    float2 fa = __half22float2(*(__half2*)&u.x);
    float2 fb = __half22float2(*(__half2*)&u.y);
    return make_float4(fa.x, fa.y, fb.x, fb.y);
}
__device__ __forceinline__ __half2 shfl_h2(__half2 v, int src) {
    uint32_t u = *(uint32_t*)&v;
    u = __shfl_sync(0xffffffffu, u, src);
    return *(__half2*)&u;
}
__device__ __forceinline__ __half2 shfl_xor_h2(__half2 v, int m) {
    uint32_t u = *(uint32_t*)&v;
    u = __shfl_xor_sync(0xffffffffu, u, m);
    return *(__half2*)&u;
}

// ---------------- scratch globals --------------------------------------------
__device__ float g_P2A1[3 * HD];
__device__ float g_c1[HD];
__device__ __align__(16) __half g_QKVh[NPTS * NCAT];       // fp16 [QA|KA|V]
__device__ __align__(16) __half g_feath[NPTS * CIN];       // fp16 features
__device__ __align__(16) __half g_WcatPh[NCAT * CIN];      // fp16 [n][k] folded
__device__ __align__(16) __half g_WoutPh[HD * HD];         // fp16 [n][k]
__device__ __align__(16) __half g_fusedh[NPTS * HD];       // fp16 fused

// ---------------- setup + feature convert (merged, one launch) ---------------
#define SETUP_BLKS (CIN + 1 + HD)          // 193
#define CONV_ITEMS (NPTS * CIN / 4)        // 262144
__global__ void setup_kernel(const float* __restrict__ Wq, const float* __restrict__ Wk,
                             const float* __restrict__ Wv, const float* __restrict__ A1,
                             const float* __restrict__ P2, const float* __restrict__ b1,
                             const float* __restrict__ bp2, const float* __restrict__ Wout,
                             const float* __restrict__ feat) {
    int c = threadIdx.x;          // 0..383
    int blk = blockIdx.x;
    if (blk < CIN) {
        int r = blk;
        float acc;
        if (c < 2 * HD) {
            const float* w = (c < HD) ? (Wq + r * HD) : (Wk + r * HD);
            int cc = c & (HD - 1);
            float a0 = 0.f, a1 = 0.f, a2 = 0.f, a3 = 0.f;
#pragma unroll 8
            for (int j = 0; j < HD; j += 4) {
                a0 = fmaf(w[j],     A1[j * HD + cc],       a0);
                a1 = fmaf(w[j + 1], A1[(j + 1) * HD + cc], a1);
                a2 = fmaf(w[j + 2], A1[(j + 2) * HD + cc], a2);
                a3 = fmaf(w[j + 3], A1[(j + 3) * HD + cc], a3);
            }
            acc = (a0 + a1) + (a2 + a3);
        } else {
            acc = Wv[r * HD + (c - 2 * HD)];
        }
        g_WcatPh[c * CIN + r] = __float2half_rn(acc);
    } else if (blk == CIN) {
        if (c < HD) {
            for (int rr = 0; rr < 3; rr++) {
                float a0 = 0.f, a1 = 0.f, a2 = 0.f, a3 = 0.f;
#pragma unroll 8
                for (int j = 0; j < HD; j += 4) {
                    a0 = fmaf(P2[rr * HD + j],     A1[j * HD + c],       a0);
                    a1 = fmaf(P2[rr * HD + j + 1], A1[(j + 1) * HD + c], a1);
                    a2 = fmaf(P2[rr * HD + j + 2], A1[(j + 2) * HD + c], a2);
                    a3 = fmaf(P2[rr * HD + j + 3], A1[(j + 3) * HD + c], a3);
                }
                g_P2A1[rr * HD + c] = (a0 + a1) + (a2 + a3);
            }
            float a0 = b1[c], a1 = 0.f, a2 = 0.f, a3 = 0.f;
#pragma unroll 8
            for (int j = 0; j < HD; j += 4) {
                a0 = fmaf(bp2[j],     A1[j * HD + c],       a0);
                a1 = fmaf(bp2[j + 1], A1[(j + 1) * HD + c], a1);
                a2 = fmaf(bp2[j + 2], A1[(j + 2) * HD + c], a2);
                a3 = fmaf(bp2[j + 3], A1[(j + 3) * HD + c], a3);
            }
            g_c1[c] = (a0 + a1) + (a2 + a3);
        }
    } else if (blk < SETUP_BLKS) {
        int n = blk - CIN - 1;    // 0..127
        if (c < HD)
            g_WoutPh[n * HD + c] = __float2half_rn(Wout[c * HD + n]);
    } else {
        int e = (blk - SETUP_BLKS) * 384 + c;
        if (e < CONV_ITEMS) {
            float4 v = ((const float4*)feat)[e];
            uint2 o;
            *(__half2*)&o.x = __floats2half2_rn(v.x, v.y);
            *(__half2*)&o.y = __floats2half2_rn(v.z, v.w);
            ((uint2*)g_feath)[e] = o;
        }
    }
}

// ---------------- fp16 mma GEMM, 2-stage cp.async pipeline (R12) --------------
// Tile 32(M) x 64(N), 128 thr (4 warps), warp computes 16x32.
template <int KTOT, int LDA, int LDB, int LDC, bool HASBIAS, bool HALFOUT>
__global__ void __launch_bounds__(128) mma_gemm_kernel(const __half* __restrict__ A,
                                                       const __half* __restrict__ B,
                                                       const float* __restrict__ bias,
                                                       void* __restrict__ Cv) {
    constexpr int NCH = KTOT / 64;
    __shared__ __align__(16) char sA[2][4096];   // 32 rows x 64 halves (swizzled)
    __shared__ __align__(16) char sB[2][8192];   // 64 rows x 64 halves

    const int tid = threadIdx.x, wid = tid >> 5, lane = tid & 31;
    const int row0 = blockIdx.x * 32, col0 = blockIdx.y * 64;
    const int wm = (wid & 1) * 16, wn = (wid >> 1) * 32;
    const uint32_t sAb = smem_to_u32(sA), sBb = smem_to_u32(sB);

    float c[4][4];
#pragma unroll
    for (int nt = 0; nt < 4; nt++)
#pragma unroll
        for (int q = 0; q < 4; q++) c[nt][q] = 0.f;

    const uint32_t lrow = lane & 15;
    const uint32_t lcb  = (lane >> 4) * 16;
    const int lr0 = tid >> 3, lc0 = tid & 7;

    auto issue_load = [&](int ch, int st) {
#pragma unroll
        for (int u = 0; u < 2; u++) {
            int r = lr0 + u * 16;
            uint32_t off = SWZ((uint32_t)(r * 128 + lc0 * 16));
            CP_ASYNC16(sAb + st * 4096 + off,
                       A + (size_t)(row0 + r) * LDA + ch * 64 + lc0 * 8);
        }
#pragma unroll
        for (int u = 0; u < 4; u++) {
            int r = lr0 + u * 16;
            uint32_t off = SWZ((uint32_t)(r * 128 + lc0 * 16));
            CP_ASYNC16(sBb + st * 8192 + off,
                       B + (size_t)(col0 + r) * LDB + ch * 64 + lc0 * 8);
        }
        CP_COMMIT();
    };

    issue_load(0, 0);

#pragma unroll
    for (int ch = 0; ch < NCH; ch++) {
        const int st = ch & 1;
        if (ch + 1 < NCH) {
            issue_load(ch + 1, st ^ 1);
            CP_WAIT(1);
        } else {
            CP_WAIT(0);
        }
        __syncthreads();

#pragma unroll
        for (int k16 = 0; k16 < 4; k16++) {
            uint32_t a[4], bf[2][4];
            {
                uint32_t b = SWZ((wm + lrow) * 128 + k16 * 32 + lcb);
                LDSM_X4(a[0], a[1], a[2], a[3], sAb + st * 4096 + b);
            }
#pragma unroll
            for (int np = 0; np < 2; np++) {
                uint32_t b = SWZ((wn + np * 16 + lrow) * 128 + k16 * 32 + lcb);
                LDSM_X4(bf[np][0], bf[np][1], bf[np][2], bf[np][3], sBb + st * 8192 + b);
            }
#pragma unroll
            for (int nt = 0; nt < 4; nt++)
                MMA_F16(c[nt], a, bf[nt >> 1][nt & 1], bf[nt >> 1][(nt & 1) + 2]);
        }
        if (ch + 1 < NCH) __syncthreads();
    }

    // epilogue
    {
        int r = row0 + wm + (lane >> 2);
#pragma unroll
        for (int nt = 0; nt < 4; nt++) {
            int cc = col0 + wn + nt * 8 + (lane & 3) * 2;
            if (HALFOUT) {
                __half* C = (__half*)Cv;
                *(__half2*)(C + (size_t)r * LDC + cc) =
                    __floats2half2_rn(c[nt][0], c[nt][1]);
                *(__half2*)(C + (size_t)(r + 8) * LDC + cc) =
                    __floats2half2_rn(c[nt][2], c[nt][3]);
            } else {
                float* C = (float*)Cv;
                float bx = 0.f, by = 0.f;
                if (HASBIAS) { bx = bias[cc]; by = bias[cc + 1]; }
                *(float2*)(C + (size_t)r * LDC + cc) =
                    make_float2(c[nt][0] + bx, c[nt][1] + by);
                *(float2*)(C + (size_t)(r + 8) * LDC + cc) =
                    make_float2(c[nt][2] + bx, c[nt][3] + by);
            }
        }
    }
}

// ---------------- fused attention kernel: one warp per point (R12 version) ---
__global__ void __launch_bounds__(128, 7) attn_kernel(const float* __restrict__ xyzs,
                                                      const int* __restrict__ kg,
                                                      const float* __restrict__ A2,
                                                      const float* __restrict__ P1,
                                                      const float* __restrict__ bp1,
                                                      const float* __restrict__ P2,
                                                      const float* __restrict__ bp2) {
    const unsigned FULL = 0xffffffffu;
    const int warp = threadIdx.x >> 5;
    const int lane = threadIdx.x & 31;
    const int pt   = blockIdx.x * 4 + warp;
    const int bN   = pt & ~(NN - 1);
    const int c0   = lane * 4;

    // ---- upfront: per-lane neighbor prep (lane l -> neighbor l&15) ----
    int rowoff_l;
    float t0_l, t1_l, t2_l;
    __half2 t01h_l, t2h_l;
    {
        int idx = kg[(size_t)pt * NK + (lane & 15)];
        rowoff_l = (bN + idx) * NCAT;
        const float* nx = xyzs + (size_t)(bN + idx) * 3;
        float cx = xyzs[(size_t)pt * 3 + 0];
        float cy = xyzs[(size_t)pt * 3 + 1];
        float cz = xyzs[(size_t)pt * 3 + 2];
        float rx = cx - nx[0], ry = cy - nx[1], rz = cz - nx[2];
        t0_l = fmaxf(fmaf(rx, P1[0], fmaf(ry, P1[3], fmaf(rz, P1[6], bp1[0]))), 0.f);
        t1_l = fmaxf(fmaf(rx, P1[1], fmaf(ry, P1[4], fmaf(rz, P1[7], bp1[1]))), 0.f);
        t2_l = fmaxf(fmaf(rx, P1[2], fmaf(ry, P1[5], fmaf(rz, P1[8], bp1[2]))), 0.f);
        t01h_l = __floats2half2_rn(t0_l, t1_l);
        t2h_l  = __float2half2_rn(t2_l);
    }

    // per-lane channel constants (packed half2)
    __half2 hb0, hb1;
    __half2 hp[3][2];
    __half2 a01[4], a23[4];
    {
        uint2 qa = *(const uint2*)(g_QKVh + (size_t)pt * NCAT + c0);
        float4 c1 = *(const float4*)(g_c1 + c0);
        hb0 = __hadd2(*(__half2*)&qa.x, __floats2half2_rn(c1.x, c1.y));
        hb1 = __hadd2(*(__half2*)&qa.y, __floats2half2_rn(c1.z, c1.w));
#pragma unroll
        for (int r = 0; r < 3; r++) {
            float4 v = *(const float4*)(g_P2A1 + r * HD + c0);
            hp[r][0] = __floats2half2_rn(v.x, v.y);
            hp[r][1] = __floats2half2_rn(v.z, v.w);
        }
#pragma unroll
        for (int i = 0; i < 4; i++) {
            float4 a2v = *(const float4*)(A2 + (c0 + i) * 4);
            a01[i] = __floats2half2_rn(a2v.x, a2v.y);
            a23[i] = __floats2half2_rn(a2v.z, a2v.w);
        }
    }
    const __half2 z2 = __float2half2_rn(0.f);
    const bool hi = (lane & 16) != 0;

    __half2 lku0 = z2, lku1 = z2;   // packed logits; extract after loop

    // ---- pass 1: per-neighbor logits (half2 math) ----
#pragma unroll
    for (int k = 0; k < NK; k++) {
        int rowoff = __shfl_sync(FULL, rowoff_l, k);
        __half2 t01 = shfl_h2(t01h_l, k);
        __half2 tb2 = shfl_h2(t2h_l, k);
        __half2 tb0 = __low2half2(t01);
        __half2 tb1 = __high2half2(t01);
        uint2 kau = *(const uint2*)(g_QKVh + rowoff + HD + c0);
        __half2 h0 = __hsub2(hb0, *(__half2*)&kau.x);
        __half2 h1 = __hsub2(hb1, *(__half2*)&kau.y);
        h0 = __hfma2(tb0, hp[0][0], h0);
        h0 = __hfma2(tb1, hp[1][0], h0);
        h0 = __hfma2(tb2, hp[2][0], h0);
        h1 = __hfma2(tb0, hp[0][1], h1);
        h1 = __hfma2(tb1, hp[1][1], h1);
        h1 = __hfma2(tb2, hp[2][1], h1);
        __half2 r0 = __hmax2(h0, z2);
        __half2 r1 = __hmax2(h1, z2);
        __half2 q01 = z2, q23 = z2, b;
        b = __low2half2(r0);  q01 = __hfma2(b, a01[0], q01); q23 = __hfma2(b, a23[0], q23);
        b = __high2half2(r0); q01 = __hfma2(b, a01[1], q01); q23 = __hfma2(b, a23[1], q23);
        b = __low2half2(r1);  q01 = __hfma2(b, a01[2], q01); q23 = __hfma2(b, a23[2], q23);
        b = __high2half2(r1); q01 = __hfma2(b, a01[3], q01); q23 = __hfma2(b, a23[3], q23);
        __half2 sel = hi ? q01 : q23;
        __half2 oth = hi ? q23 : q01;
        __half2 u = __hadd2(oth, shfl_xor_h2(sel, 16));
        u = __hadd2(u, shfl_xor_h2(u, 8));
        u = __hadd2(u, shfl_xor_h2(u, 4));
        u = __hadd2(u, shfl_xor_h2(u, 2));
        u = __hadd2(u, shfl_xor_h2(u, 1));
        if ((lane & 7) == (k & 7)) {
            if (k < 8) lku0 = u; else lku1 = u;
        }
    }
    // extract this lane's head (lane&8 -> high half)
    float lk0 = (lane & 8) ? __high2float(lku0) : __low2float(lku0);
    float lk1 = (lane & 8) ? __high2float(lku1) : __low2float(lku1);

    // ---- softmax: head h in 8-lane group [8h, 8h+7], 2 logits/lane ----
    float mx = fmaxf(lk0, lk1);
    mx = fmaxf(mx, __shfl_xor_sync(FULL, mx, 4));
    mx = fmaxf(mx, __shfl_xor_sync(FULL, mx, 2));
    mx = fmaxf(mx, __shfl_xor_sync(FULL, mx, 1));
    float e0 = __expf(lk0 - mx), e1 = __expf(lk1 - mx);
    float s = e0 + e1;
    s += __shfl_xor_sync(FULL, s, 4);
    s += __shfl_xor_sync(FULL, s, 2);
    s += __shfl_xor_sync(FULL, s, 1);
    float inv = __fdividef(1.f, s);
    float a0 = e0 * inv, a1 = e1 * inv;

    // ---- factored pe reduction ----
    float S0, S1, S2, S3;
    {
        int kk = lane & 7;
        float ua = __shfl_sync(FULL, t0_l, kk);
        float ub = __shfl_sync(FULL, t0_l, kk + 8);
        S0 = a0 * ua + a1 * ub;
        ua = __shfl_sync(FULL, t1_l, kk);
        ub = __shfl_sync(FULL, t1_l, kk + 8);
        S1 = a0 * ua + a1 * ub;
        ua = __shfl_sync(FULL, t2_l, kk);
        ub = __shfl_sync(FULL, t2_l, kk + 8);
        S2 = a0 * ua + a1 * ub;
        S3 = a0 + a1;
#pragma unroll
        for (int m = 4; m >= 1; m >>= 1) {
            S0 += __shfl_xor_sync(FULL, S0, m);
            S1 += __shfl_xor_sync(FULL, S1, m);
            S2 += __shfl_xor_sync(FULL, S2, m);
            S3 += __shfl_xor_sync(FULL, S3, m);
        }
    }

    float accv[4];
    {
        float4 v0 = *(const float4*)(P2 + 0 * HD + c0);
        float4 v1 = *(const float4*)(P2 + 1 * HD + c0);
        float4 v2 = *(const float4*)(P2 + 2 * HD + c0);
        float4 vb = *(const float4*)(bp2 + c0);
        accv[0] = fmaf(S0, v0.x, fmaf(S1, v1.x, fmaf(S2, v2.x, S3 * vb.x)));
        accv[1] = fmaf(S0, v0.y, fmaf(S1, v1.y, fmaf(S2, v2.y, S3 * vb.y)));
        accv[2] = fmaf(S0, v0.z, fmaf(S1, v1.z, fmaf(S2, v2.z, S3 * vb.z)));
        accv[3] = fmaf(S0, v0.w, fmaf(S1, v1.w, fmaf(S2, v2.w, S3 * vb.w)));
    }

    const int hsrc = lane & 24;

    // ---- pass 2: weighted V reduce ----
#pragma unroll
    for (int k = 0; k < NK; k++) {
        float asel = (k < 8) ? a0 : a1;
        float aw = __shfl_sync(FULL, asel, hsrc | (k & 7));
        int rowoff = __shfl_sync(FULL, rowoff_l, k);
        float4 vv = ldh4(g_QKVh + rowoff + 2 * HD + c0);
        accv[0] = fmaf(aw, vv.x, accv[0]);
        accv[1] = fmaf(aw, vv.y, accv[1]);
        accv[2] = fmaf(aw, vv.z, accv[2]);
        accv[3] = fmaf(aw, vv.w, accv[3]);
    }

    {
        uint2 o;
        *(__half2*)&o.x = __floats2half2_rn(accv[0], accv[1]);
        *(__half2*)&o.y = __floats2half2_rn(accv[2], accv[3]);
        *(uint2*)(g_fusedh + (size_t)pt * HD + c0) = o;
    }
}

// ======================= launch =============================================
extern "C" void kernel_launch(void* const* d_in, const int* in_sizes, int n_in,
                              void* d_out, int out_size) {
    const float* xyzs     = (const float*)d_in[0];
    const float* features = (const float*)d_in[1];
    const int*   kg       = (const int*)d_in[2];
    const float* Wk   = (const float*)d_in[3];
    const float* Wv   = (const float*)d_in[4];
    const float* Wq   = (const float*)d_in[5];
    const float* A1   = (const float*)d_in[6];
    const float* b1   = (const float*)d_in[7];
    const float* A2   = (const float*)d_in[8];
    const float* P1   = (const float*)d_in[10];
    const float* bp1  = (const float*)d_in[11];
    const float* P2   = (const float*)d_in[12];
    const float* bp2  = (const float*)d_in[13];
    const float* Wout = (const float*)d_in[14];
    const float* bout = (const float*)d_in[15];
    float* out = (float*)d_out;

    __half *pQKVh, *pFeath, *pWcatPh, *pWoutPh, *pFusedh;
    cudaGetSymbolAddress((void**)&pQKVh,   g_QKVh);
    cudaGetSymbolAddress((void**)&pFeath,  g_feath);
    cudaGetSymbolAddress((void**)&pWcatPh, g_WcatPh);
    cudaGetSymbolAddress((void**)&pWoutPh, g_WoutPh);
    cudaGetSymbolAddress((void**)&pFusedh, g_fusedh);

    const int conv_blks = (CONV_ITEMS + 383) / 384;
    setup_kernel<<<SETUP_BLKS + conv_blks, 384>>>(Wq, Wk, Wv, A1, P2, b1, bp2,
                                                  Wout, features);

    // QKV: [16384 x 64] @ [384 x 64]^T -> fp16 [16384 x 384]   (3072 blocks)
    mma_gemm_kernel<CIN, CIN, CIN, NCAT, false, true>
        <<<dim3(NPTS / 32, NCAT / 64), 128>>>(pFeath, pWcatPh, nullptr, pQKVh);

    attn_kernel<<<NPTS / 4, 128>>>(xyzs, kg, A2, P1, bp1, P2, bp2);

    // out: [16384 x 128] @ [128 x 128]^T + bout -> fp32        (1024 blocks)
    mma_gemm_kernel<HD, HD, HD, COUT, true, false>
        <<<dim3(NPTS / 32, COUT / 64), 128>>>(pFusedh, pWoutPh, bout, out);
}